// round 6
// baseline (speedup 1.0000x reference)
#include <cuda_runtime.h>

// CenterIdLoss: out = sum_c cnt_c * (LSE(center_c) - center_c[c]) * NUM_POS / N^2
// center_c = mean of feat rows with label == c.
// feat: [8192, 4096] f32, label: [8192] int32 OR int64 (runtime-detected).

#define CDIM  4096
#define NSAMP 8192
#define SLOTS 96
// NUM_POS / (N*N) = 4 / 8192^2 = 2^-24
#define SCALE 5.9604644775390625e-08f

__device__ int   g_cursor[CDIM];
__device__ int   g_idx[CDIM * SLOTS];
__device__ float g_loss[CDIM];   // cnt_c * (LSE - diag) per class; 0 for empty classes
__device__ int   g_is64;         // 1 if label buffer is int64, 0 if int32

// ---------------------------------------------------------------- init
__global__ void init_k() {
    int t = blockIdx.x * blockDim.x + threadIdx.x;
    if (t < CDIM) { g_cursor[t] = 0; g_loss[t] = 0.0f; }
    if (t == 0) g_is64 = 1;
}

// ---------------------------------------------------------------- dtype detect
// Reads the first 4096 int64 slots = 32 KB, which is in-bounds whether the
// buffer is int64 (64 KB) or int32 (32 KB). If labels are int32, a slot fuses
// two labels; any nonzero high word pushes the value out of [0, CDIM) and we
// flip to int32 mode. Deterministic for fixed input.
__global__ void detect_k(const long long* __restrict__ lab) {
    int i = blockIdx.x * blockDim.x + threadIdx.x;
    if (i < NSAMP / 2) {
        long long v = lab[i];
        if (v < 0 || v >= CDIM) g_is64 = 0;   // idempotent store, no race hazard
    }
}

// ---------------------------------------------------------------- scatter
__global__ void scatter_k(const void* __restrict__ labp) {
    int i = blockIdx.x * blockDim.x + threadIdx.x;
    if (i < NSAMP) {
        int c = g_is64 ? (int)((const long long*)labp)[i]
                       : ((const int*)labp)[i];
        if ((unsigned)c < CDIM) {
            int slot = atomicAdd(&g_cursor[c], 1);
            if (slot < SLOTS) g_idx[c * SLOTS + slot] = i;
        }
    }
}

// ---------------------------------------------------------------- sort (deterministic fp sum order)
__global__ void sort_k() {
    int c = blockIdx.x * blockDim.x + threadIdx.x;
    if (c >= CDIM) return;
    int cnt = g_cursor[c];
    if (cnt > SLOTS) cnt = SLOTS;
    int* a = &g_idx[c * SLOTS];
    for (int i = 1; i < cnt; i++) {
        int v = a[i];
        int j = i - 1;
        while (j >= 0 && a[j] > v) { a[j + 1] = a[j]; j--; }
        a[j + 1] = v;
    }
}

// ---------------------------------------------------------------- main: per-class mean + LSE + diag
__global__ void __launch_bounds__(256) lse_k(const float* __restrict__ feat) {
    int c = blockIdx.x;
    int cnt = g_cursor[c];
    if (cnt == 0) return;              // uniform across block: safe
    if (cnt > SLOTS) cnt = SLOTS;
    int t = threadIdx.x;

    // 16 columns per thread: chunk k covers cols [k*1024, k*1024+1024),
    // thread t owns float4 at cols k*1024 + 4t .. +3  -> acc[4k + e]
    float acc[16];
    #pragma unroll
    for (int k = 0; k < 16; k++) acc[k] = 0.0f;

    for (int r = 0; r < cnt; r++) {
        const float4* row = reinterpret_cast<const float4*>(
            feat + (size_t)g_idx[c * SLOTS + r] * CDIM);
        #pragma unroll
        for (int k = 0; k < 4; k++) {
            float4 v = __ldg(&row[k * 256 + t]);
            acc[4 * k + 0] += v.x;
            acc[4 * k + 1] += v.y;
            acc[4 * k + 2] += v.z;
            acc[4 * k + 3] += v.w;
        }
    }

    float inv = 1.0f / (float)cnt;
    float m = -3.402823e38f;
    #pragma unroll
    for (int k = 0; k < 16; k++) {
        acc[k] *= inv;                 // center value
        m = fmaxf(m, acc[k]);
    }

    __shared__ float s_diag;
    __shared__ float s_max[8];
    __shared__ float s_sum[8];

    // diagonal element center_c[c]
    {
        int kk  = c >> 10;             // chunk index 0..3
        int rem = c & 1023;
        if (t == (rem >> 2)) s_diag = acc[4 * kk + (rem & 3)];
    }

    // block max reduce
    float wm = m;
    #pragma unroll
    for (int o = 16; o; o >>= 1)
        wm = fmaxf(wm, __shfl_xor_sync(0xffffffffu, wm, o));
    if ((t & 31) == 0) s_max[t >> 5] = wm;
    __syncthreads();
    float bm = s_max[0];
    #pragma unroll
    for (int w = 1; w < 8; w++) bm = fmaxf(bm, s_max[w]);

    // sum of exp(center - max)
    float se = 0.0f;
    #pragma unroll
    for (int k = 0; k < 16; k++) se += expf(acc[k] - bm);
    #pragma unroll
    for (int o = 16; o; o >>= 1)
        se += __shfl_xor_sync(0xffffffffu, se, o);
    if ((t & 31) == 0) s_sum[t >> 5] = se;
    __syncthreads();

    if (t == 0) {
        float tot = 0.0f;
        #pragma unroll
        for (int w = 0; w < 8; w++) tot += s_sum[w];
        float lse = bm + logf(tot);
        g_loss[c] = (float)cnt * (lse - s_diag);
    }
}

// ---------------------------------------------------------------- deterministic final reduce
// Single block; fixed tree order -> bit-identical result on every replay.
__global__ void __launch_bounds__(1024) reduce_k(float* __restrict__ out) {
    __shared__ float s[1024];
    int t = threadIdx.x;
    float v = g_loss[t] + g_loss[t + 1024] + g_loss[t + 2048] + g_loss[t + 3072];
    s[t] = v;
    __syncthreads();
    #pragma unroll
    for (int o = 512; o > 0; o >>= 1) {
        if (t < o) s[t] += s[t + o];
        __syncthreads();
    }
    if (t == 0) out[0] = s[0] * SCALE;
}

// ---------------------------------------------------------------- launch
extern "C" void kernel_launch(void* const* d_in, const int* in_sizes, int n_in,
                              void* d_out, int out_size) {
    const float* feat = (const float*)d_in[0];   // [8192*4096] f32
    const void*  lab  = d_in[1];                 // [8192] i32 or i64
    float* out = (float*)d_out;

    init_k<<<(CDIM + 255) / 256, 256>>>();
    detect_k<<<(NSAMP / 2 + 255) / 256, 256>>>((const long long*)lab);
    scatter_k<<<(NSAMP + 255) / 256, 256>>>(lab);
    sort_k<<<(CDIM + 255) / 256, 256>>>();
    lse_k<<<CDIM, 256>>>(feat);
    reduce_k<<<1, 1024>>>(out);
}